// round 17
// baseline (speedup 1.0000x reference)
#include <cuda_runtime.h>
#include <cuda_bf16.h>
#include <math.h>

#define NN 512
#define NBATCH 128
#define EPS 1e-8f
#define S_CAP 304
#define PK_CAP ((S_CAP*(S_CAP+1))/2)
#define PBW_SM (S_CAP-32)
#define PK_FULL ((NN*(NN+1))/2)
#define NTB 512
#define NWB 16
#define DYN_B ((PK_CAP + 32*PBW_SM)*4)
#define U65 (64*65)
#define ZA_SMEM (4*U65*4)                 /* 66560 B */

// ---------------- device scratch ----------------
__device__ float g_L[NN*NN];
__device__ float g_Z[NN*NN];
__device__ float g_Minv[8][64*64];
__device__ float g_zpart[8];
__device__ float g_bres[NBATCH];
__device__ int   g_fd[8];
__device__ int   g_fs[64];                 /* [q*8 + j] : X(j,q) published */
__device__ __align__(16) float g_fbA[(size_t)NBATCH * PK_FULL];
__device__ __align__(16) float g_fbPB[(size_t)NBATCH * 32 * NN];

// =====================================================================
// K1: L = B^T B + eps I ; Z = L + I.  Also zeroes the zall flags.
// =====================================================================
__global__ __launch_bounds__(256) void k_gemm(const float* __restrict__ B)
{
    __shared__ float SA[16][64];
    __shared__ float SB[16][64];
    const int tid = threadIdx.x;
    const int tx = tid & 15, ty = tid >> 4;
    const int i0 = blockIdx.y * 64, j0 = blockIdx.x * 64;

    if (blockIdx.x == 0 && blockIdx.y == 0) {
        if (tid < 8)  g_fd[tid] = 0;
        if (tid < 64) g_fs[tid] = 0;
    }

    float acc[4][4];
#pragma unroll
    for (int r = 0; r < 4; ++r)
#pragma unroll
        for (int c = 0; c < 4; ++c) acc[r][c] = 0.f;

    for (int kc = 0; kc < NN; kc += 16) {
        for (int e = tid; e < 16*64; e += 256) {
            int kk = e >> 6, ii = e & 63;
            SA[kk][ii] = B[(kc+kk)*NN + i0 + ii];
            SB[kk][ii] = B[(kc+kk)*NN + j0 + ii];
        }
        __syncthreads();
#pragma unroll
        for (int kk = 0; kk < 16; ++kk) {
            float a[4], bb[4];
#pragma unroll
            for (int r = 0; r < 4; ++r) a[r]  = SA[kk][ty*4 + r];
#pragma unroll
            for (int c = 0; c < 4; ++c) bb[c] = SB[kk][tx*4 + c];
#pragma unroll
            for (int r = 0; r < 4; ++r)
#pragma unroll
                for (int c = 0; c < 4; ++c) acc[r][c] += a[r] * bb[c];
        }
        __syncthreads();
    }
#pragma unroll
    for (int r = 0; r < 4; ++r)
#pragma unroll
        for (int c = 0; c < 4; ++c) {
            int gi = i0 + ty*4 + r, gj = j0 + tx*4 + c;
            float v = acc[r][c] + ((gi == gj) ? EPS : 0.f);
            g_L[gi*NN + gj] = v;
            g_Z[gi*NN + gj] = v + ((gi == gj) ? 1.f : 0.f);
        }
}

// =====================================================================
// Per-batch blocked Cholesky (nb=32). (unchanged)
// =====================================================================
__global__ __launch_bounds__(NTB) void k_batch(const int* __restrict__ x)
{
    extern __shared__ float dynsm[];
    __shared__ int   sidx[NN];
    __shared__ short spos[NN];
    __shared__ unsigned char sact[NN];
    __shared__ float s_inv[32];
    __shared__ int   s_rbD[32];
    __shared__ int   s_sh;

    const int b = blockIdx.x;
    const int tid = threadIdx.x, warp = tid >> 5, lane = tid & 31;

    if (tid < 32) {
        int cnt = 0;
        for (int base = 0; base < NN; base += 32) {
            int g = base + lane;
            int v = (x[b*NN + g] != 0);
            unsigned m = __ballot_sync(0xffffffffu, v);
            int p = cnt + __popc(m & ((1u << lane) - 1u));
            if (v) sidx[p] = g;
            spos[g] = (short)p;
            sact[g] = (unsigned char)v;
            cnt += __popc(m);
        }
        if (lane == 0) s_sh = cnt;
    }
    __syncthreads();
    const int s = s_sh;
    const bool fits = (s <= S_CAP);
    float* A  = fits ? dynsm            : &g_fbA [(size_t)b * PK_FULL];
    float* PB = fits ? (dynsm + PK_CAP) : &g_fbPB[(size_t)b * 32 * NN];
    const int pbw = fits ? PBW_SM : NN;

    for (int i = warp; i < s; i += NWB) {
        const float* Lrow = &g_L[sidx[i] * NN];
        const int rb = (i * (i + 1)) >> 1;
        const int glim = sidx[i] + 1;
        for (int g = lane; g < glim; g += 32) {
            float v = Lrow[g];
            if (sact[g]) A[rb + spos[g]] = v;
        }
    }
    __syncthreads();

    float lsum = 0.f;
    for (int j0 = 0; j0 < s; j0 += 32) {
        const int nbj = (s - j0 < 32) ? (s - j0) : 32;
        if (tid < nbj)
            s_rbD[tid] = (((j0 + tid) * (j0 + tid + 1)) >> 1) + j0;
        __syncthreads();

        if (warp == 0) {
            const int row = j0 + lane;
            const bool act = (lane < nbj);
            const int rbI = act ? ((row * (row + 1)) >> 1) : 0;
            float v[32];
#pragma unroll
            for (int k = 0; k < 32; ++k)
                v[k] = (act && k <= lane && k < nbj) ? A[rbI + j0 + k] : 0.f;

#pragma unroll
            for (int j = 0; j < 32; ++j) {
                if (j >= nbj) break;
                float dj = __shfl_sync(0xffffffffu, v[j], j);
                float d = sqrtf(dj);
                float inv = 1.f / d;
                if (lane == j) { v[j] = d; s_inv[j] = inv; }
                else if (lane > j) v[j] *= inv;
                float cj = (lane > j) ? v[j] : 0.f;
#pragma unroll
                for (int k = j + 1; k < 32; ++k) {
                    float cjk = __shfl_sync(0xffffffffu, cj, k);
                    v[k] -= cj * cjk;
                }
                if (lane == 0) lsum += logf(d);
            }
#pragma unroll
            for (int k = 0; k < 32; ++k)
                if (act && k <= lane && k < nbj) A[rbI + j0 + k] = v[k];
        }
        __syncthreads();

        const int j1 = j0 + 32;
        if (j1 >= s) break;
        const int nrows = s - j1;

        for (int i = j1 + tid; i < s; i += NTB) {
            const int rbI = (i * (i + 1)) >> 1;
            float v[32];
#pragma unroll
            for (int j = 0; j < 32; ++j) v[j] = A[rbI + j0 + j];
#pragma unroll
            for (int j = 0; j < 32; ++j) {
                float acc0 = v[j], acc1 = 0.f;
                const float* dr = &A[s_rbD[j]];
#pragma unroll
                for (int m = 0; m + 1 < j; m += 2) {
                    acc0 -= v[m]   * dr[m];
                    acc1 -= v[m+1] * dr[m+1];
                }
                if (j & 1) acc0 -= v[j-1] * dr[j-1];
                v[j] = (acc0 + acc1) * s_inv[j];
            }
            const int col = i - j1;
#pragma unroll
            for (int j = 0; j < 32; ++j) PB[j * pbw + col] = v[j];
        }
        __syncthreads();

        const int RT = (nrows + 7) >> 3;
        for (int ti = warp; ti < RT; ti += NWB) {
            const int ar = 8 * ti;
            const int ktmax = 2 * ti + 2;
            for (int kt = lane; kt < ktmax; kt += 32) {
                const int bc = 4 * kt;
                float acc[8][4];
#pragma unroll
                for (int qr = 0; qr < 8; ++qr)
#pragma unroll
                    for (int qc = 0; qc < 4; ++qc) acc[qr][qc] = 0.f;
#pragma unroll
                for (int j = 0; j < 32; ++j) {
                    const float* pr = &PB[j * pbw];
                    float4 a0 = *(const float4*)&pr[ar];
                    float4 a1 = *(const float4*)&pr[ar + 4];
                    float4 bv = *(const float4*)&pr[bc];
                    float av[8] = {a0.x,a0.y,a0.z,a0.w,a1.x,a1.y,a1.z,a1.w};
                    float bb[4] = {bv.x,bv.y,bv.z,bv.w};
#pragma unroll
                    for (int qr = 0; qr < 8; ++qr)
#pragma unroll
                        for (int qc = 0; qc < 4; ++qc)
                            acc[qr][qc] += av[qr] * bb[qc];
                }
#pragma unroll
                for (int qr = 0; qr < 8; ++qr) {
                    const int r = j1 + ar + qr;
                    if (r < s) {
                        const int rb = (r * (r + 1)) >> 1;
#pragma unroll
                        for (int qc = 0; qc < 4; ++qc) {
                            const int c = j1 + bc + qc;
                            if (c <= r) A[rb + c] -= acc[qr][qc];
                        }
                    }
                }
            }
        }
        __syncthreads();
    }
    if (tid == 0) g_bres[b] = 2.f * lsum;
}

// =====================================================================
// Z helpers (all 512-thread, smem ld 65)
// =====================================================================
__device__ __forceinline__ float factor64_smem(float* D, float* s_dinv,
                                               int tid, int warp, int lane)
{
    float lsum = 0.f;
#pragma unroll
    for (int cb = 0; cb < 64; cb += 32) {
        if (warp == 0) {
            float v[32];
#pragma unroll
            for (int k = 0; k < 32; ++k)
                v[k] = (k <= lane) ? D[(cb + lane)*65 + cb + k] : 0.f;
#pragma unroll
            for (int j = 0; j < 32; ++j) {
                float dj = __shfl_sync(0xffffffffu, v[j], j);
                float d = sqrtf(dj);
                float inv = 1.f / d;
                if (lane == j) { v[j] = d; s_dinv[j] = inv; }
                else if (lane > j) v[j] *= inv;
                float cj = (lane > j) ? v[j] : 0.f;
#pragma unroll
                for (int k = j + 1; k < 32; ++k) {
                    float cjk = __shfl_sync(0xffffffffu, cj, k);
                    v[k] -= cj * cjk;
                }
                if (lane == 0) lsum += logf(d);
            }
#pragma unroll
            for (int k = 0; k < 32; ++k)
                if (k <= lane) D[(cb + lane)*65 + cb + k] = v[k];
        }
        __syncthreads();

        if (cb == 0) {
            if (tid < 32) {
                const int i = 32 + tid;
                float v[32];
#pragma unroll
                for (int j = 0; j < 32; ++j) v[j] = D[i*65 + j];
#pragma unroll
                for (int j = 0; j < 32; ++j) {
                    float acc = v[j];
                    const float* dr = &D[j*65];
#pragma unroll
                    for (int m = 0; m < j; ++m) acc -= v[m] * dr[m];
                    v[j] = acc * s_dinv[j];
                }
#pragma unroll
                for (int j = 0; j < 32; ++j) D[i*65 + j] = v[j];
            }
            __syncthreads();
            {
                const int r  = 32 + (tid >> 4);
                const int c0 = 32 + ((tid & 15) << 1);
                float a0 = 0.f, a1 = 0.f;
#pragma unroll
                for (int k = 0; k < 32; ++k) {
                    float ar = D[r*65 + k];
                    a0 += ar * D[c0*65 + k];
                    a1 += ar * D[(c0+1)*65 + k];
                }
                D[r*65 + c0]     -= a0;
                D[r*65 + c0 + 1] -= a1;
            }
            __syncthreads();
        }
    }
    return lsum;
}

// Invert factored lower 64x64 L (ld65) into M (ld65). T = 32x33 temp.
__device__ __forceinline__ void invert64(const float* L, float* M, float* T, int tid)
{
    const int warp = tid >> 5, lane = tid & 31;
    for (int e = tid; e < 64*65; e += 512) M[e] = 0.f;
    __syncthreads();

    if (warp < 2) {
        const int base = warp * 32;
        float y[32];
#pragma unroll
        for (int k = 0; k < 32; ++k) {
            float s = (k == lane) ? 1.0f : 0.0f;
#pragma unroll
            for (int m = 0; m < 32; ++m)
                if (m < k) s -= L[(base + k)*65 + base + m] * y[m];
            y[k] = s / L[(base + k)*65 + base + k];
        }
#pragma unroll
        for (int k = 0; k < 32; ++k)
            M[(base + k)*65 + base + lane] = y[k];
    }
    __syncthreads();

    {   // T = L21 * M1
        const int r  = tid >> 4;
        const int c2 = (tid & 15) << 1;
        float t0 = 0.f, t1 = 0.f;
#pragma unroll
        for (int m = 0; m < 32; ++m) {
            float lv = L[(32 + r)*65 + m];
            t0 += lv * M[m*65 + c2];
            t1 += lv * M[m*65 + c2 + 1];
        }
        T[r*33 + c2] = t0; T[r*33 + c2 + 1] = t1;
    }
    __syncthreads();
    {   // M21 = -M2 * T
        const int r  = tid >> 4;
        const int c2 = (tid & 15) << 1;
        float s0 = 0.f, s1 = 0.f;
#pragma unroll
        for (int m = 0; m < 32; ++m) {
            float mv = M[(32 + r)*65 + 32 + m];
            s0 += mv * T[m*33 + c2];
            s1 += mv * T[m*33 + c2 + 1];
        }
        M[(32 + r)*65 + c2]     = -s0;
        M[(32 + r)*65 + c2 + 1] = -s1;
    }
    __syncthreads();
}

// O = A * M^T (all ld65), 2x4 tiles, 512 threads.
__device__ __forceinline__ void gemm64_ABt(float* O, const float* A, const float* M, int tid)
{
    const int tx = tid & 15, ty = tid >> 4;
    float acc[2][4];
#pragma unroll
    for (int r = 0; r < 2; ++r)
#pragma unroll
        for (int c = 0; c < 4; ++c) acc[r][c] = 0.f;
#pragma unroll
    for (int k = 0; k < 64; ++k) {
        float a[2], bb[4];
#pragma unroll
        for (int r = 0; r < 2; ++r) a[r]  = A[(ty*2 + r)*65 + k];
#pragma unroll
        for (int c = 0; c < 4; ++c) bb[c] = M[(tx*4 + c)*65 + k];
#pragma unroll
        for (int r = 0; r < 2; ++r)
#pragma unroll
            for (int c = 0; c < 4; ++c) acc[r][c] += a[r] * bb[c];
    }
#pragma unroll
    for (int r = 0; r < 2; ++r)
#pragma unroll
        for (int c = 0; c < 4; ++c)
            O[(ty*2 + r)*65 + tx*4 + c] = acc[r][c];
}

// gmem block dst (row stride NN) -= A·B^T  (A,B smem ld65); ldcg RMW.
__device__ __forceinline__ void rmw64(float* dst, const float* A, const float* B, int tid)
{
    const int tx = tid & 15, ty = tid >> 4;
    float acc[2][4];
#pragma unroll
    for (int r = 0; r < 2; ++r)
#pragma unroll
        for (int c = 0; c < 4; ++c) acc[r][c] = 0.f;
#pragma unroll
    for (int k = 0; k < 64; ++k) {
        float a[2], bb[4];
#pragma unroll
        for (int r = 0; r < 2; ++r) a[r]  = A[(ty*2 + r)*65 + k];
#pragma unroll
        for (int c = 0; c < 4; ++c) bb[c] = B[(tx*4 + c)*65 + k];
#pragma unroll
        for (int r = 0; r < 2; ++r)
#pragma unroll
            for (int c = 0; c < 4; ++c) acc[r][c] += a[r] * bb[c];
    }
#pragma unroll
    for (int r = 0; r < 2; ++r)
#pragma unroll
        for (int c = 0; c < 4; ++c) {
            float* p = &dst[(ty*2 + r)*NN + tx*4 + c];
            *p = __ldcg(p) - acc[r][c];
        }
}

__device__ __forceinline__ void waitflag(int* f, int tid)
{
    if (tid == 0) { while (atomicAdd(f, 0) == 0) {} }
    __syncthreads();
}

// =====================================================================
// k_zall: whole Z Cholesky logdet in ONE launch. grid=7 CTAs (row i=bx+1),
// flag-synced. Diag blocks factored+inverted; solves are GEMMs vs inverse;
// trailing updates RMW in gmem (ldcg). Nothing downstream reads L blocks.
// =====================================================================
__global__ __launch_bounds__(512) void k_zall()
{
    extern __shared__ float sm[];
    float* M  = sm;             // Minv of current column's diag
    float* W  = sm + U65;       // general buffer
    float* Xi = sm + 2*U65;     // this row's solved block
    float* W2 = sm + 3*U65;     // peer X / invert temp
    __shared__ float s_dinv[32];
    const int tid = threadIdx.x, warp = tid >> 5, lane = tid & 31;
    const int i = blockIdx.x + 1;

    if (i == 1) {
        // bootstrap: factor + invert diag 0
        for (int e = tid; e < 64*64; e += 512) {
            int r = e >> 6, c = e & 63;
            W[r*65 + c] = g_Z[r*NN + c];
        }
        __syncthreads();
        float l0 = factor64_smem(W, s_dinv, tid, warp, lane);
        if (tid == 0) g_zpart[0] = 2.f * l0;
        __syncthreads();
        invert64(W, M, W2, tid);
        for (int e = tid; e < 64*64; e += 512)
            g_Minv[0][e] = M[(e >> 6)*65 + (e & 63)];
        __syncthreads();
        __threadfence();
        if (tid == 0) atomicExch(&g_fd[0], 1);
        __syncthreads();
    }

    for (int q = 0; q < i; ++q) {
        if (!(i == 1 && q == 0)) {
            waitflag(&g_fd[q], tid);
            for (int e = tid; e < 64*64; e += 512)
                M[(e >> 6)*65 + (e & 63)] = __ldcg(&g_Minv[q][e]);
        }
        for (int e = tid; e < 64*64; e += 512) {
            int r = e >> 6, c = e & 63;
            W[r*65 + c] = __ldcg(&g_Z[(64*i + r)*NN + 64*q + c]);
        }
        __syncthreads();
        gemm64_ABt(Xi, W, M, tid);
        __syncthreads();
        for (int e = tid; e < 64*64; e += 512) {
            int r = e >> 6, c = e & 63;
            g_Z[(64*i + r)*NN + 64*q + c] = Xi[r*65 + c];
        }
        __syncthreads();
        __threadfence();
        if (tid == 0) atomicExch(&g_fs[q*8 + i], 1);
        __syncthreads();

        // trailing updates for this row: (i,j) -= Xi·Xj^T, j=q+1..i
        for (int j = q + 1; j <= i; ++j) {
            const float* Xj;
            if (j < i) {
                waitflag(&g_fs[q*8 + j], tid);
                for (int e = tid; e < 64*64; e += 512) {
                    int r = e >> 6, c = e & 63;
                    W2[r*65 + c] = __ldcg(&g_Z[(64*j + r)*NN + 64*q + c]);
                }
                __syncthreads();
                Xj = W2;
            } else {
                Xj = Xi;
            }
            rmw64(&g_Z[(size_t)(64*i)*NN + 64*j], Xi, Xj, tid);
            __syncthreads();
        }
    }

    // factor own diag (fully updated), publish inverse for successors
    for (int e = tid; e < 64*64; e += 512) {
        int r = e >> 6, c = e & 63;
        W[r*65 + c] = __ldcg(&g_Z[(64*i + r)*NN + 64*i + c]);
    }
    __syncthreads();
    float ls = factor64_smem(W, s_dinv, tid, warp, lane);
    if (tid == 0) g_zpart[i] = 2.f * ls;
    __syncthreads();
    if (i < 7) {
        invert64(W, M, W2, tid);
        for (int e = tid; e < 64*64; e += 512)
            g_Minv[i][e] = M[(e >> 6)*65 + (e & 63)];
        __syncthreads();
        __threadfence();
        if (tid == 0) atomicExch(&g_fd[i], 1);
    }
}

// =====================================================================
__global__ void k_combine(float* __restrict__ out)
{
    __shared__ float z;
    if (threadIdx.x == 0) {
        float t = 0.f;
        for (int p = 0; p < 8; ++p) t += g_zpart[p];
        z = t;
    }
    __syncthreads();
    if (threadIdx.x < NBATCH)
        out[threadIdx.x] = g_bres[threadIdx.x] - z;
}

// =====================================================================
extern "C" void kernel_launch(void* const* d_in, const int* in_sizes, int n_in,
                              void* d_out, int out_size)
{
    const int* x = (const int*)d_in[0];
    const float* Bm = (const float*)d_in[1];
    if (in_sizes[0] == NN*NN && in_sizes[1] == NBATCH*NN) {
        x  = (const int*)d_in[1];
        Bm = (const float*)d_in[0];
    }
    float* out = (float*)d_out;

    cudaFuncSetAttribute(k_batch, cudaFuncAttributeMaxDynamicSharedMemorySize, DYN_B);
    cudaFuncSetAttribute(k_zall,  cudaFuncAttributeMaxDynamicSharedMemorySize, ZA_SMEM);

    cudaStream_t s2;
    cudaStreamCreateWithFlags(&s2, cudaStreamNonBlocking);
    cudaEvent_t eg, e2;
    cudaEventCreateWithFlags(&eg, cudaEventDisableTiming);
    cudaEventCreateWithFlags(&e2, cudaEventDisableTiming);

    k_gemm<<<dim3(8,8), 256>>>(Bm);                 // #1 (main; zeroes flags)
    cudaEventRecord(eg, 0);
    cudaStreamWaitEvent(s2, eg, 0);
    k_zall<<<7, 512, ZA_SMEM, s2>>>();              // #2 (s2, one launch)
    cudaEventRecord(e2, s2);
    k_batch<<<NBATCH, NTB, DYN_B>>>(x);             // #3 (main)
    cudaStreamWaitEvent(0, e2, 0);
    k_combine<<<1, 128>>>(out);                     // #4 (main)

    cudaStreamCaptureStatus st = cudaStreamCaptureStatusNone;
    cudaStreamIsCapturing(0, &st);
    if (st == cudaStreamCaptureStatusNone) {
        cudaEventDestroy(eg); cudaEventDestroy(e2);
        cudaStreamDestroy(s2);
    }
}